// round 1
// baseline (speedup 1.0000x reference)
#include <cuda_runtime.h>

#define S 512
#define H 768
#define NH 12
#define HD 64

// ---------------- scratch (static device memory; no allocation) ----------------
__device__ float g_qp[S * H];            // query proj [s][c]
__device__ float g_kp[S * H];            // key proj
__device__ float g_vp[S * H];            // value proj
__device__ float g_tt[NH * S * H];       // t[h][q][e]
__device__ float g_cb[NH * S];           // cb[h][q]
__device__ float g_score[NH * S * S];    // score/attn [h][q][k]

// ---------------- f32x2 helpers ----------------
__device__ __forceinline__ unsigned long long pack2(float a, float b) {
    unsigned long long r;
    asm("mov.b64 %0, {%1, %2};" : "=l"(r) : "r"(__float_as_uint(a)), "r"(__float_as_uint(b)));
    return r;
}
__device__ __forceinline__ void unpack2(unsigned long long v, float& a, float& b) {
    unsigned int x, y;
    asm("mov.b64 {%0, %1}, %2;" : "=r"(x), "=r"(y) : "l"(v));
    a = __uint_as_float(x); b = __uint_as_float(y);
}
__device__ __forceinline__ unsigned long long ffma2(unsigned long long a, unsigned long long b,
                                                    unsigned long long c) {
    unsigned long long d;
    asm("fma.rn.f32x2 %0, %1, %2, %3;" : "=l"(d) : "l"(a), "l"(b), "l"(c));
    return d;
}

// ---------------- 1) QKV projections: C = A @ W^T + b  (512x768, K=768) ----------------
__global__ void __launch_bounds__(128) proj_kernel(
    const float* __restrict__ q_in, const float* __restrict__ k_in, const float* __restrict__ v_in,
    const float* __restrict__ Wq, const float* __restrict__ bq,
    const float* __restrict__ Wk, const float* __restrict__ bk,
    const float* __restrict__ Wv, const float* __restrict__ bv)
{
    const float* A; const float* W; const float* bias; float* C;
    if (blockIdx.z == 0)      { A = q_in; W = Wq; bias = bq; C = g_qp; }
    else if (blockIdx.z == 1) { A = k_in; W = Wk; bias = bk; C = g_kp; }
    else                      { A = v_in; W = Wv; bias = bv; C = g_vp; }

    const int s0 = blockIdx.x * 64;
    const int c0 = blockIdx.y * 64;
    const int tid = threadIdx.x;

    __shared__ float As[64][17];   // [s][k]
    __shared__ float Ws[16][68];   // [k][c]

    const int sg = tid >> 3;   // 0..15 -> rows sg*4..+3
    const int cg = tid & 7;    // 0..7  -> cols cg*8..+7 (4 pairs)

    unsigned long long acc[4][4];
#pragma unroll
    for (int i = 0; i < 4; i++)
#pragma unroll
        for (int j = 0; j < 4; j++) acc[i][j] = 0ULL;

    for (int k0 = 0; k0 < H; k0 += 16) {
#pragma unroll
        for (int t = 0; t < 2; t++) {
            int f = tid + t * 128;
            int r = f >> 2;
            int cc = (f & 3) * 4;
            float4 v4 = *reinterpret_cast<const float4*>(&A[(s0 + r) * H + k0 + cc]);
            As[r][cc + 0] = v4.x; As[r][cc + 1] = v4.y; As[r][cc + 2] = v4.z; As[r][cc + 3] = v4.w;
        }
#pragma unroll
        for (int t = 0; t < 2; t++) {
            int f = tid + t * 128;
            int c = f >> 2;
            int kk = (f & 3) * 4;
            float4 v4 = *reinterpret_cast<const float4*>(&W[(c0 + c) * H + k0 + kk]);
            Ws[kk + 0][c] = v4.x; Ws[kk + 1][c] = v4.y; Ws[kk + 2][c] = v4.z; Ws[kk + 3][c] = v4.w;
        }
        __syncthreads();
#pragma unroll
        for (int kk = 0; kk < 16; kk++) {
            unsigned long long bv4[4];
#pragma unroll
            for (int j = 0; j < 4; j++)
                bv4[j] = *reinterpret_cast<const unsigned long long*>(&Ws[kk][cg * 8 + 2 * j]);
#pragma unroll
            for (int i = 0; i < 4; i++) {
                float a = As[sg * 4 + i][kk];
                unsigned long long aa = pack2(a, a);
#pragma unroll
                for (int j = 0; j < 4; j++) acc[i][j] = ffma2(aa, bv4[j], acc[i][j]);
            }
        }
        __syncthreads();
    }
#pragma unroll
    for (int i = 0; i < 4; i++) {
        int s = s0 + sg * 4 + i;
#pragma unroll
        for (int j = 0; j < 4; j++) {
            float lo, hi; unpack2(acc[i][j], lo, hi);
            int c = c0 + cg * 8 + 2 * j;
            float2 r2; r2.x = lo + bias[c]; r2.y = hi + bias[c + 1];
            *reinterpret_cast<float2*>(&C[s * H + c]) = r2;
        }
    }
}

// ---------------- 2) t[h][q][e] = sum_d (qp + vb) * Wr[h*64+d][e] ----------------
__global__ void __launch_bounds__(128) tt_kernel(const float* __restrict__ Wr,
                                                 const float* __restrict__ v_bias)
{
    const int e0 = blockIdx.x * 64;
    const int q0 = blockIdx.y * 16;
    const int tid = threadIdx.x;

    __shared__ float Qs[16][68];   // [q][d]
    __shared__ float Ws[64][68];   // [d][e]

    const int qg = tid >> 3;   // 0..15
    const int eg = tid & 7;    // e block eg*8..+7

    for (int h = 0; h < NH; h++) {
        // stage Qs (16x64): 256 float4, 2 per thread
#pragma unroll
        for (int t = 0; t < 2; t++) {
            int f = tid + t * 128;
            int q = f >> 4;
            int d4 = (f & 15) * 4;
            float4 a = *reinterpret_cast<const float4*>(&g_qp[(q0 + q) * H + h * HD + d4]);
            float4 b = *reinterpret_cast<const float4*>(&v_bias[h * HD + d4]);
            a.x += b.x; a.y += b.y; a.z += b.z; a.w += b.w;
            *reinterpret_cast<float4*>(&Qs[q][d4]) = a;
        }
        // stage Ws (64x64): 1024 float4, 8 per thread
#pragma unroll
        for (int t = 0; t < 8; t++) {
            int f = tid + t * 128;
            int d = f >> 4;
            int e4 = (f & 15) * 4;
            float4 a = *reinterpret_cast<const float4*>(&Wr[(h * HD + d) * H + e0 + e4]);
            *reinterpret_cast<float4*>(&Ws[d][e4]) = a;
        }
        __syncthreads();

        unsigned long long acc[4] = {0ULL, 0ULL, 0ULL, 0ULL};
#pragma unroll
        for (int d = 0; d < HD; d++) {
            float a = Qs[qg][d];
            unsigned long long aa = pack2(a, a);
#pragma unroll
            for (int j = 0; j < 4; j++) {
                unsigned long long bv =
                    *reinterpret_cast<const unsigned long long*>(&Ws[d][eg * 8 + 2 * j]);
                acc[j] = ffma2(aa, bv, acc[j]);
            }
        }
        float* dst = &g_tt[(h * S + q0 + qg) * H + e0 + eg * 8];
#pragma unroll
        for (int j = 0; j < 4; j++)
            *reinterpret_cast<unsigned long long*>(&dst[2 * j]) = acc[j];
        __syncthreads();
    }
}

// ---------------- 2b) cb[h][q] = sum_d (qp + vb) * br ----------------
__global__ void __launch_bounds__(128) cbias_kernel(const float* __restrict__ br,
                                                    const float* __restrict__ v_bias)
{
    int idx = blockIdx.x * blockDim.x + threadIdx.x;
    if (idx >= NH * S) return;
    int h = idx / S, q = idx % S;
    float s = 0.f;
#pragma unroll 8
    for (int d = 0; d < HD; d++)
        s += (g_qp[q * H + h * HD + d] + v_bias[h * HD + d]) * br[h * HD + d];
    g_cb[idx] = s;
}

// ---------------- 3) AC[h][q][k] = sum_d (qp + u) * kp  (into g_score) ----------------
__global__ void __launch_bounds__(128) ac_kernel(const float* __restrict__ u_bias)
{
    const int k0 = blockIdx.x * 64;
    const int q0 = blockIdx.y * 64;
    const int h  = blockIdx.z;
    const int tid = threadIdx.x;

    __shared__ float Qs[64][68];   // [q][d]
    __shared__ float Ks[64][66];   // [d][k]

    const int sg = tid >> 3;   // 0..15 -> q rows sg*4..+3
    const int kg = tid & 7;    // k cols kg*8..+7

    // stage Qs (+u): 1024 float4 / 128 = 8
#pragma unroll
    for (int t = 0; t < 8; t++) {
        int f = tid + t * 128;
        int q = f >> 4;
        int d4 = (f & 15) * 4;
        float4 a = *reinterpret_cast<const float4*>(&g_qp[(q0 + q) * H + h * HD + d4]);
        float4 u = *reinterpret_cast<const float4*>(&u_bias[h * HD + d4]);
        a.x += u.x; a.y += u.y; a.z += u.z; a.w += u.w;
        *reinterpret_cast<float4*>(&Qs[q][d4]) = a;
    }
    // stage Ks transposed
#pragma unroll
    for (int t = 0; t < 8; t++) {
        int f = tid + t * 128;
        int k = f >> 4;
        int d4 = (f & 15) * 4;
        float4 a = *reinterpret_cast<const float4*>(&g_kp[(k0 + k) * H + h * HD + d4]);
        Ks[d4 + 0][k] = a.x; Ks[d4 + 1][k] = a.y; Ks[d4 + 2][k] = a.z; Ks[d4 + 3][k] = a.w;
    }
    __syncthreads();

    unsigned long long acc[4][4];
#pragma unroll
    for (int i = 0; i < 4; i++)
#pragma unroll
        for (int j = 0; j < 4; j++) acc[i][j] = 0ULL;

#pragma unroll
    for (int d = 0; d < HD; d++) {
        unsigned long long bv4[4];
#pragma unroll
        for (int j = 0; j < 4; j++)
            bv4[j] = *reinterpret_cast<const unsigned long long*>(&Ks[d][kg * 8 + 2 * j]);
#pragma unroll
        for (int i = 0; i < 4; i++) {
            float a = Qs[sg * 4 + i][d];
            unsigned long long aa = pack2(a, a);
#pragma unroll
            for (int j = 0; j < 4; j++) acc[i][j] = ffma2(aa, bv4[j], acc[i][j]);
        }
    }
#pragma unroll
    for (int i = 0; i < 4; i++) {
        int q = q0 + sg * 4 + i;
#pragma unroll
        for (int j = 0; j < 4; j++) {
            int k = k0 + kg * 8 + 2 * j;
            *reinterpret_cast<unsigned long long*>(&g_score[(h * S + q) * S + k]) = acc[i][j];
        }
    }
}

// ---------------- 4) BD + fuse: score = (AC + cb + sum_e pos*t) / 8 ----------------
// grid (2, 512): one q per block-row, 256 keys per block; 128 threads (2 keys each)
#define BD_TS (H * NH)            // 9216 floats t2s [e][h]
#define BD_PS (32 * 257)          // pos tile  [e][k] pad 257
#define BD_SMEM_BYTES ((BD_TS + BD_PS) * 4)

__global__ void __launch_bounds__(128) bd_kernel(const float* __restrict__ pos)
{
    extern __shared__ float sm[];
    float* t2s  = sm;            // [e*12 + h]
    float* poss = sm + BD_TS;    // [e*257 + k]

    const int q   = blockIdx.y;
    const int k0  = blockIdx.x * 256;
    const int tid = threadIdx.x;

    // stage t2s: transpose g_tt[h][q][e] -> t2s[e][h]; 2304 float4 / 128 = 18
#pragma unroll
    for (int t = 0; t < 18; t++) {
        int f = tid + t * 128;
        int h = f / 192;
        int r = f - h * 192;
        int e = r * 4;
        float4 v4 = *reinterpret_cast<const float4*>(&g_tt[(h * S + q) * H + e]);
        t2s[(e + 0) * 12 + h] = v4.x;
        t2s[(e + 1) * 12 + h] = v4.y;
        t2s[(e + 2) * 12 + h] = v4.z;
        t2s[(e + 3) * 12 + h] = v4.w;
    }

    unsigned long long acc0[6], acc1[6];
#pragma unroll
    for (int j = 0; j < 6; j++) { acc0[j] = 0ULL; acc1[j] = 0ULL; }

    const float* prow = pos + ((long)q * S + k0) * H;

    for (int ch = 0; ch < 24; ch++) {
        __syncthreads();
        const int e0 = ch * 32;
        // stage pos chunk: 256k x 32e = 2048 float4 / 128 = 16
#pragma unroll
        for (int t = 0; t < 16; t++) {
            int f = tid + t * 128;
            int kk = f >> 3;
            int e4 = (f & 7) * 4;
            float4 v4 = *reinterpret_cast<const float4*>(&prow[kk * H + e0 + e4]);
            poss[(e4 + 0) * 257 + kk] = v4.x;
            poss[(e4 + 1) * 257 + kk] = v4.y;
            poss[(e4 + 2) * 257 + kk] = v4.z;
            poss[(e4 + 3) * 257 + kk] = v4.w;
        }
        __syncthreads();
#pragma unroll
        for (int ee = 0; ee < 32; ee++) {
            const int e = e0 + ee;
            float p0 = poss[ee * 257 + tid];
            float p1 = poss[ee * 257 + tid + 128];
            unsigned long long pp0 = pack2(p0, p0);
            unsigned long long pp1 = pack2(p1, p1);
            const ulonglong2 w0 = *reinterpret_cast<const ulonglong2*>(&t2s[e * 12 + 0]);
            const ulonglong2 w1 = *reinterpret_cast<const ulonglong2*>(&t2s[e * 12 + 4]);
            const ulonglong2 w2 = *reinterpret_cast<const ulonglong2*>(&t2s[e * 12 + 8]);
            acc0[0] = ffma2(pp0, w0.x, acc0[0]);
            acc0[1] = ffma2(pp0, w0.y, acc0[1]);
            acc0[2] = ffma2(pp0, w1.x, acc0[2]);
            acc0[3] = ffma2(pp0, w1.y, acc0[3]);
            acc0[4] = ffma2(pp0, w2.x, acc0[4]);
            acc0[5] = ffma2(pp0, w2.y, acc0[5]);
            acc1[0] = ffma2(pp1, w0.x, acc1[0]);
            acc1[1] = ffma2(pp1, w0.y, acc1[1]);
            acc1[2] = ffma2(pp1, w1.x, acc1[2]);
            acc1[3] = ffma2(pp1, w1.y, acc1[3]);
            acc1[4] = ffma2(pp1, w2.x, acc1[4]);
            acc1[5] = ffma2(pp1, w2.y, acc1[5]);
        }
    }

    const int ka = k0 + tid;
    const int kb = k0 + tid + 128;
#pragma unroll
    for (int j = 0; j < 6; j++) {
        float a0, a1, b0, b1;
        unpack2(acc0[j], a0, a1);   // key ka, heads 2j, 2j+1
        unpack2(acc1[j], b0, b1);   // key kb
        int h0 = 2 * j, h1 = 2 * j + 1;
        float c0 = g_cb[h0 * S + q];
        float c1 = g_cb[h1 * S + q];
        int i0 = (h0 * S + q) * S;
        int i1 = (h1 * S + q) * S;
        g_score[i0 + ka] = (g_score[i0 + ka] + c0 + a0) * 0.125f;
        g_score[i1 + ka] = (g_score[i1 + ka] + c1 + a1) * 0.125f;
        g_score[i0 + kb] = (g_score[i0 + kb] + c0 + b0) * 0.125f;
        g_score[i1 + kb] = (g_score[i1 + kb] + c1 + b1) * 0.125f;
    }
}

// ---------------- 5) softmax over k with mask ----------------
__global__ void __launch_bounds__(128) softmax_kernel(const int* __restrict__ key_mask)
{
    const int q = blockIdx.x, h = blockIdx.y;
    float* row = g_score + (h * S + q) * S;
    const int tid = threadIdx.x;

    float v[4];
    float mx = -1e30f;
#pragma unroll
    for (int i = 0; i < 4; i++) {
        int k = tid + i * 128;
        float x = row[k];
        if (key_mask[k] == 0) x = -1e15f;
        v[i] = x;
        mx = fmaxf(mx, x);
    }
#pragma unroll
    for (int o = 16; o > 0; o >>= 1) mx = fmaxf(mx, __shfl_xor_sync(0xffffffffu, mx, o));
    __shared__ float redm[4];
    if ((tid & 31) == 0) redm[tid >> 5] = mx;
    __syncthreads();
    mx = fmaxf(fmaxf(redm[0], redm[1]), fmaxf(redm[2], redm[3]));

    float s = 0.f;
#pragma unroll
    for (int i = 0; i < 4; i++) { v[i] = __expf(v[i] - mx); s += v[i]; }
#pragma unroll
    for (int o = 16; o > 0; o >>= 1) s += __shfl_xor_sync(0xffffffffu, s, o);
    __shared__ float reds[4];
    if ((tid & 31) == 0) reds[tid >> 5] = s;
    __syncthreads();
    s = (reds[0] + reds[1]) + (reds[2] + reds[3]);
    float inv = 1.0f / s;
#pragma unroll
    for (int i = 0; i < 4; i++) row[tid + i * 128] = v[i] * inv;
}

// ---------------- 6) out[q][h*64+d] = sum_k attn[h][q][k] * vp[k][h*64+d] ----------------
__global__ void __launch_bounds__(128) out_kernel(float* __restrict__ out)
{
    const int q0 = blockIdx.x * 16;
    const int h  = blockIdx.y;
    const int tid = threadIdx.x;

    __shared__ float As[16][36];   // [q][k chunk]
    __shared__ float Vs[32][68];   // [k][d]

    const int qg = tid >> 3;
    const int dg = tid & 7;        // d0 = dg*8

    unsigned long long acc[4] = {0ULL, 0ULL, 0ULL, 0ULL};

    for (int kc = 0; kc < 16; kc++) {
        {
            int f = tid;
            int qq = f >> 3;
            int k4 = (f & 7) * 4;
            float4 a = *reinterpret_cast<const float4*>(&g_score[(h * S + q0 + qq) * S + kc * 32 + k4]);
            *reinterpret_cast<float4*>(&As[qq][k4]) = a;
        }
#pragma unroll
        for (int t = 0; t < 4; t++) {
            int f = tid + t * 128;
            int k = f >> 4;
            int d4 = (f & 15) * 4;
            float4 a = *reinterpret_cast<const float4*>(&g_vp[(kc * 32 + k) * H + h * HD + d4]);
            *reinterpret_cast<float4*>(&Vs[k][d4]) = a;
        }
        __syncthreads();
#pragma unroll
        for (int kk = 0; kk < 32; kk++) {
            float a = As[qg][kk];
            unsigned long long aa = pack2(a, a);
            ulonglong2 w0 = *reinterpret_cast<const ulonglong2*>(&Vs[kk][dg * 8]);
            ulonglong2 w1 = *reinterpret_cast<const ulonglong2*>(&Vs[kk][dg * 8 + 4]);
            acc[0] = ffma2(aa, w0.x, acc[0]);
            acc[1] = ffma2(aa, w0.y, acc[1]);
            acc[2] = ffma2(aa, w1.x, acc[2]);
            acc[3] = ffma2(aa, w1.y, acc[3]);
        }
        __syncthreads();
    }
    float r[8];
#pragma unroll
    for (int j = 0; j < 4; j++) unpack2(acc[j], r[2 * j], r[2 * j + 1]);
    float* dst = &out[(q0 + qg) * H + h * HD + dg * 8];
    *reinterpret_cast<float4*>(&dst[0]) = make_float4(r[0], r[1], r[2], r[3]);
    *reinterpret_cast<float4*>(&dst[4]) = make_float4(r[4], r[5], r[6], r[7]);
}

// ---------------- launch ----------------
extern "C" void kernel_launch(void* const* d_in, const int* in_sizes, int n_in,
                              void* d_out, int out_size)
{
    (void)in_sizes; (void)n_in; (void)out_size;
    const float* key      = (const float*)d_in[0];
    const float* query    = (const float*)d_in[1];
    const float* value    = (const float*)d_in[2];
    const float* pos      = (const float*)d_in[3];
    const int*   key_mask = (const int*)d_in[4];
    const float* Wk = (const float*)d_in[5];
    const float* bk = (const float*)d_in[6];
    const float* Wq = (const float*)d_in[7];
    const float* bq = (const float*)d_in[8];
    const float* Wv = (const float*)d_in[9];
    const float* bv = (const float*)d_in[10];
    const float* Wr = (const float*)d_in[11];
    const float* br = (const float*)d_in[12];
    const float* u_bias = (const float*)d_in[13];
    const float* v_bias = (const float*)d_in[14];
    float* out = (float*)d_out;

    proj_kernel<<<dim3(8, 12, 3), 128>>>(query, key, value, Wq, bq, Wk, bk, Wv, bv);
    tt_kernel<<<dim3(12, 32), 128>>>(Wr, v_bias);
    cbias_kernel<<<48, 128>>>(br, v_bias);
    ac_kernel<<<dim3(8, 8, 12), 128>>>(u_bias);

    cudaFuncSetAttribute(bd_kernel, cudaFuncAttributeMaxDynamicSharedMemorySize, BD_SMEM_BYTES);
    bd_kernel<<<dim3(2, S), 128, BD_SMEM_BYTES>>>(pos);

    softmax_kernel<<<dim3(S, NH), 128>>>(key_mask);
    out_kernel<<<dim3(32, NH), 128>>>(out);
}

// round 2
// speedup vs baseline: 1.3067x; 1.3067x over previous
#include <cuda_runtime.h>

#define S 512
#define H 768
#define NH 12
#define HD 64

// ---------------- scratch (static device memory; no allocation) ----------------
__device__ float g_qp[S * H];            // query proj [s][c]
__device__ float g_kp[S * H];            // key proj
__device__ float g_vp[S * H];            // value proj
__device__ float g_tt[NH * S * H];       // t[h][q][e]
__device__ float g_cb[NH * S];           // cb[h][q]
__device__ float g_score[NH * S * S];    // score/attn [h][q][k]

// ---------------- f32x2 helpers ----------------
__device__ __forceinline__ unsigned long long pack2(float a, float b) {
    unsigned long long r;
    asm("mov.b64 %0, {%1, %2};" : "=l"(r) : "r"(__float_as_uint(a)), "r"(__float_as_uint(b)));
    return r;
}
__device__ __forceinline__ void unpack2(unsigned long long v, float& a, float& b) {
    unsigned int x, y;
    asm("mov.b64 {%0, %1}, %2;" : "=r"(x), "=r"(y) : "l"(v));
    a = __uint_as_float(x); b = __uint_as_float(y);
}
__device__ __forceinline__ unsigned long long ffma2(unsigned long long a, unsigned long long b,
                                                    unsigned long long c) {
    unsigned long long d;
    asm("fma.rn.f32x2 %0, %1, %2, %3;" : "=l"(d) : "l"(a), "l"(b), "l"(c));
    return d;
}
__device__ __forceinline__ void cp_async16(unsigned int smem_addr, const void* gptr) {
    asm volatile("cp.async.cg.shared.global [%0], [%1], 16;" :: "r"(smem_addr), "l"(gptr));
}
__device__ __forceinline__ void cp_commit() {
    asm volatile("cp.async.commit_group;" ::: "memory");
}
template <int N>
__device__ __forceinline__ void cp_wait() {
    asm volatile("cp.async.wait_group %0;" :: "n"(N) : "memory");
}

// ---------------- 1) QKV projections: C = A @ W^T + b  (512x768, K=768) ----------------
__global__ void __launch_bounds__(128) proj_kernel(
    const float* __restrict__ q_in, const float* __restrict__ k_in, const float* __restrict__ v_in,
    const float* __restrict__ Wq, const float* __restrict__ bq,
    const float* __restrict__ Wk, const float* __restrict__ bk,
    const float* __restrict__ Wv, const float* __restrict__ bv)
{
    const float* A; const float* W; const float* bias; float* C;
    if (blockIdx.z == 0)      { A = q_in; W = Wq; bias = bq; C = g_qp; }
    else if (blockIdx.z == 1) { A = k_in; W = Wk; bias = bk; C = g_kp; }
    else                      { A = v_in; W = Wv; bias = bv; C = g_vp; }

    const int s0 = blockIdx.x * 64;
    const int c0 = blockIdx.y * 64;
    const int tid = threadIdx.x;

    __shared__ float As[64][17];   // [s][k]
    __shared__ float Ws[16][68];   // [k][c]

    const int sg = tid >> 3;   // 0..15 -> rows sg*4..+3
    const int cg = tid & 7;    // 0..7  -> cols cg*8..+7 (4 pairs)

    unsigned long long acc[4][4];
#pragma unroll
    for (int i = 0; i < 4; i++)
#pragma unroll
        for (int j = 0; j < 4; j++) acc[i][j] = 0ULL;

    for (int k0 = 0; k0 < H; k0 += 16) {
#pragma unroll
        for (int t = 0; t < 2; t++) {
            int f = tid + t * 128;
            int r = f >> 2;
            int cc = (f & 3) * 4;
            float4 v4 = *reinterpret_cast<const float4*>(&A[(s0 + r) * H + k0 + cc]);
            As[r][cc + 0] = v4.x; As[r][cc + 1] = v4.y; As[r][cc + 2] = v4.z; As[r][cc + 3] = v4.w;
        }
#pragma unroll
        for (int t = 0; t < 2; t++) {
            int f = tid + t * 128;
            int c = f >> 2;
            int kk = (f & 3) * 4;
            float4 v4 = *reinterpret_cast<const float4*>(&W[(c0 + c) * H + k0 + kk]);
            Ws[kk + 0][c] = v4.x; Ws[kk + 1][c] = v4.y; Ws[kk + 2][c] = v4.z; Ws[kk + 3][c] = v4.w;
        }
        __syncthreads();
#pragma unroll
        for (int kk = 0; kk < 16; kk++) {
            unsigned long long bv4[4];
#pragma unroll
            for (int j = 0; j < 4; j++)
                bv4[j] = *reinterpret_cast<const unsigned long long*>(&Ws[kk][cg * 8 + 2 * j]);
#pragma unroll
            for (int i = 0; i < 4; i++) {
                float a = As[sg * 4 + i][kk];
                unsigned long long aa = pack2(a, a);
#pragma unroll
                for (int j = 0; j < 4; j++) acc[i][j] = ffma2(aa, bv4[j], acc[i][j]);
            }
        }
        __syncthreads();
    }
#pragma unroll
    for (int i = 0; i < 4; i++) {
        int s = s0 + sg * 4 + i;
#pragma unroll
        for (int j = 0; j < 4; j++) {
            float lo, hi; unpack2(acc[i][j], lo, hi);
            int c = c0 + cg * 8 + 2 * j;
            float2 r2; r2.x = lo + bias[c]; r2.y = hi + bias[c + 1];
            *reinterpret_cast<float2*>(&C[s * H + c]) = r2;
        }
    }
}

// ---------------- 2) t[h][q][e] = sum_d (qp + vb) * Wr[h*64+d][e] ----------------
__global__ void __launch_bounds__(128) tt_kernel(const float* __restrict__ Wr,
                                                 const float* __restrict__ v_bias)
{
    const int e0 = blockIdx.x * 64;
    const int q0 = blockIdx.y * 16;
    const int tid = threadIdx.x;

    __shared__ float Qs[16][68];   // [q][d]
    __shared__ float Ws[64][68];   // [d][e]

    const int qg = tid >> 3;   // 0..15
    const int eg = tid & 7;    // e block eg*8..+7

    for (int h = 0; h < NH; h++) {
#pragma unroll
        for (int t = 0; t < 2; t++) {
            int f = tid + t * 128;
            int q = f >> 4;
            int d4 = (f & 15) * 4;
            float4 a = *reinterpret_cast<const float4*>(&g_qp[(q0 + q) * H + h * HD + d4]);
            float4 b = *reinterpret_cast<const float4*>(&v_bias[h * HD + d4]);
            a.x += b.x; a.y += b.y; a.z += b.z; a.w += b.w;
            *reinterpret_cast<float4*>(&Qs[q][d4]) = a;
        }
#pragma unroll
        for (int t = 0; t < 8; t++) {
            int f = tid + t * 128;
            int d = f >> 4;
            int e4 = (f & 15) * 4;
            float4 a = *reinterpret_cast<const float4*>(&Wr[(h * HD + d) * H + e0 + e4]);
            *reinterpret_cast<float4*>(&Ws[d][e4]) = a;
        }
        __syncthreads();

        unsigned long long acc[4] = {0ULL, 0ULL, 0ULL, 0ULL};
#pragma unroll
        for (int d = 0; d < HD; d++) {
            float a = Qs[qg][d];
            unsigned long long aa = pack2(a, a);
#pragma unroll
            for (int j = 0; j < 4; j++) {
                unsigned long long bv =
                    *reinterpret_cast<const unsigned long long*>(&Ws[d][eg * 8 + 2 * j]);
                acc[j] = ffma2(aa, bv, acc[j]);
            }
        }
        float* dst = &g_tt[(h * S + q0 + qg) * H + e0 + eg * 8];
#pragma unroll
        for (int j = 0; j < 4; j++)
            *reinterpret_cast<unsigned long long*>(&dst[2 * j]) = acc[j];
        __syncthreads();
    }
}

// ---------------- 2b) cb[h][q] = sum_d (qp + vb) * br ----------------
__global__ void __launch_bounds__(128) cbias_kernel(const float* __restrict__ br,
                                                    const float* __restrict__ v_bias)
{
    int idx = blockIdx.x * blockDim.x + threadIdx.x;
    if (idx >= NH * S) return;
    int h = idx / S, q = idx % S;
    float s = 0.f;
#pragma unroll 8
    for (int d = 0; d < HD; d++)
        s += (g_qp[q * H + h * HD + d] + v_bias[h * HD + d]) * br[h * HD + d];
    g_cb[idx] = s;
}

// ---------------- 3) AC[h][q][k] = sum_d (qp + u) * kp  (into g_score) ----------------
__global__ void __launch_bounds__(128) ac_kernel(const float* __restrict__ u_bias)
{
    const int k0 = blockIdx.x * 64;
    const int q0 = blockIdx.y * 64;
    const int h  = blockIdx.z;
    const int tid = threadIdx.x;

    __shared__ float Qs[64][68];   // [q][d]
    __shared__ float Ks[64][66];   // [d][k]

    const int sg = tid >> 3;
    const int kg = tid & 7;

#pragma unroll
    for (int t = 0; t < 8; t++) {
        int f = tid + t * 128;
        int q = f >> 4;
        int d4 = (f & 15) * 4;
        float4 a = *reinterpret_cast<const float4*>(&g_qp[(q0 + q) * H + h * HD + d4]);
        float4 u = *reinterpret_cast<const float4*>(&u_bias[h * HD + d4]);
        a.x += u.x; a.y += u.y; a.z += u.z; a.w += u.w;
        *reinterpret_cast<float4*>(&Qs[q][d4]) = a;
    }
#pragma unroll
    for (int t = 0; t < 8; t++) {
        int f = tid + t * 128;
        int k = f >> 4;
        int d4 = (f & 15) * 4;
        float4 a = *reinterpret_cast<const float4*>(&g_kp[(k0 + k) * H + h * HD + d4]);
        Ks[d4 + 0][k] = a.x; Ks[d4 + 1][k] = a.y; Ks[d4 + 2][k] = a.z; Ks[d4 + 3][k] = a.w;
    }
    __syncthreads();

    unsigned long long acc[4][4];
#pragma unroll
    for (int i = 0; i < 4; i++)
#pragma unroll
        for (int j = 0; j < 4; j++) acc[i][j] = 0ULL;

#pragma unroll
    for (int d = 0; d < HD; d++) {
        unsigned long long bv4[4];
#pragma unroll
        for (int j = 0; j < 4; j++)
            bv4[j] = *reinterpret_cast<const unsigned long long*>(&Ks[d][kg * 8 + 2 * j]);
#pragma unroll
        for (int i = 0; i < 4; i++) {
            float a = Qs[sg * 4 + i][d];
            unsigned long long aa = pack2(a, a);
#pragma unroll
            for (int j = 0; j < 4; j++) acc[i][j] = ffma2(aa, bv4[j], acc[i][j]);
        }
    }
#pragma unroll
    for (int i = 0; i < 4; i++) {
        int q = q0 + sg * 4 + i;
#pragma unroll
        for (int j = 0; j < 4; j++) {
            int k = k0 + kg * 8 + 2 * j;
            *reinterpret_cast<unsigned long long*>(&g_score[(h * S + q) * S + k]) = acc[i][j];
        }
    }
}

// ---------------- 4) BD + fuse: score = (AC + cb + sum_e pos*t) / 8 ----------------
// grid (2, 512): one q per block-row, 256 keys per block; 128 threads, 2 keys each.
// pos streamed via cp.async double-buffered pipeline in natural [key][e] layout.
#define BD_E 32                   // e-chunk width
#define BD_PAD 36                 // padded row (floats)
#define BD_NCH (H / BD_E)         // 24 chunks
#define BD_TS (H * NH)            // t2s floats: [e][h]
#define BD_BUF (256 * BD_PAD)     // one pos buffer
#define BD_SMEM_BYTES ((BD_TS + 2 * BD_BUF) * 4)

__global__ void __launch_bounds__(128) bd_kernel(const float* __restrict__ pos)
{
    extern __shared__ float sm[];
    float* t2s = sm;                         // [e*12 + h]
    float* buf0 = sm + BD_TS;                // pos tile ping
    float* buf1 = sm + BD_TS + BD_BUF;       // pos tile pong

    const int q   = blockIdx.y;
    const int k0  = blockIdx.x * 256;
    const int tid = threadIdx.x;

    const float* prow = pos + ((long)q * S + k0) * H;

    // issue chunk 0 loads immediately (overlaps with t2s staging below)
    {
        unsigned int dbase = (unsigned int)__cvta_generic_to_shared(buf0);
#pragma unroll
        for (int t = 0; t < 16; t++) {
            int seg = tid + t * 128;          // 2048 segments: 256 rows x 8 float4
            int row = seg >> 3;
            int c4  = (seg & 7) * 4;
            cp_async16(dbase + (row * BD_PAD + c4) * 4, &prow[(long)row * H + c4]);
        }
        cp_commit();
    }

    // stage t2s: transpose g_tt[h][q][e] -> t2s[e][h]; 2304 float4 / 128 = 18
#pragma unroll
    for (int t = 0; t < 18; t++) {
        int f = tid + t * 128;
        int h = f / 192;
        int r = f - h * 192;
        int e = r * 4;
        float4 v4 = *reinterpret_cast<const float4*>(&g_tt[(h * S + q) * H + e]);
        t2s[(e + 0) * 12 + h] = v4.x;
        t2s[(e + 1) * 12 + h] = v4.y;
        t2s[(e + 2) * 12 + h] = v4.z;
        t2s[(e + 3) * 12 + h] = v4.w;
    }

    unsigned long long acc0[6], acc1[6];
#pragma unroll
    for (int j = 0; j < 6; j++) { acc0[j] = 0ULL; acc1[j] = 0ULL; }

    const int ka36 = tid * BD_PAD;
    const int kb36 = (tid + 128) * BD_PAD;

    for (int ch = 0; ch < BD_NCH; ch++) {
        // issue next chunk into the other buffer (its previous contents were
        // fully consumed; the trailing __syncthreads of iteration ch-1 guards it)
        if (ch + 1 < BD_NCH) {
            float* nb = ((ch + 1) & 1) ? buf1 : buf0;
            unsigned int dbase = (unsigned int)__cvta_generic_to_shared(nb);
            const float* src = prow + (ch + 1) * BD_E;
#pragma unroll
            for (int t = 0; t < 16; t++) {
                int seg = tid + t * 128;
                int row = seg >> 3;
                int c4  = (seg & 7) * 4;
                cp_async16(dbase + (row * BD_PAD + c4) * 4, &src[(long)row * H + c4]);
            }
            cp_commit();
            cp_wait<1>();     // current chunk (ch) complete, next still in flight
        } else {
            cp_wait<0>();     // last chunk: drain everything
        }
        __syncthreads();

        const float* bp = (ch & 1) ? buf1 : buf0;
        const int e0 = ch * BD_E;
#pragma unroll
        for (int j = 0; j < 8; j++) {
            float4 pa = *reinterpret_cast<const float4*>(&bp[ka36 + 4 * j]);
            float4 pb = *reinterpret_cast<const float4*>(&bp[kb36 + 4 * j]);
            const float* tw = &t2s[(e0 + 4 * j) * 12];
#pragma unroll
            for (int i = 0; i < 4; i++) {
                float p0 = (&pa.x)[i];
                float p1 = (&pb.x)[i];
                unsigned long long pp0 = pack2(p0, p0);
                unsigned long long pp1 = pack2(p1, p1);
                const ulonglong2 w0 = *reinterpret_cast<const ulonglong2*>(&tw[i * 12 + 0]);
                const ulonglong2 w1 = *reinterpret_cast<const ulonglong2*>(&tw[i * 12 + 4]);
                const ulonglong2 w2 = *reinterpret_cast<const ulonglong2*>(&tw[i * 12 + 8]);
                acc0[0] = ffma2(pp0, w0.x, acc0[0]);
                acc0[1] = ffma2(pp0, w0.y, acc0[1]);
                acc0[2] = ffma2(pp0, w1.x, acc0[2]);
                acc0[3] = ffma2(pp0, w1.y, acc0[3]);
                acc0[4] = ffma2(pp0, w2.x, acc0[4]);
                acc0[5] = ffma2(pp0, w2.y, acc0[5]);
                acc1[0] = ffma2(pp1, w0.x, acc1[0]);
                acc1[1] = ffma2(pp1, w0.y, acc1[1]);
                acc1[2] = ffma2(pp1, w1.x, acc1[2]);
                acc1[3] = ffma2(pp1, w1.y, acc1[3]);
                acc1[4] = ffma2(pp1, w2.x, acc1[4]);
                acc1[5] = ffma2(pp1, w2.y, acc1[5]);
            }
        }
        __syncthreads();
    }

    const int ka = k0 + tid;
    const int kb = k0 + tid + 128;
#pragma unroll
    for (int j = 0; j < 6; j++) {
        float a0, a1, b0, b1;
        unpack2(acc0[j], a0, a1);   // key ka, heads 2j, 2j+1
        unpack2(acc1[j], b0, b1);   // key kb
        int h0 = 2 * j, h1 = 2 * j + 1;
        float c0 = g_cb[h0 * S + q];
        float c1 = g_cb[h1 * S + q];
        int i0 = (h0 * S + q) * S;
        int i1 = (h1 * S + q) * S;
        g_score[i0 + ka] = (g_score[i0 + ka] + c0 + a0) * 0.125f;
        g_score[i1 + ka] = (g_score[i1 + ka] + c1 + a1) * 0.125f;
        g_score[i0 + kb] = (g_score[i0 + kb] + c0 + b0) * 0.125f;
        g_score[i1 + kb] = (g_score[i1 + kb] + c1 + b1) * 0.125f;
    }
}

// ---------------- 5) softmax over k with mask ----------------
__global__ void __launch_bounds__(128) softmax_kernel(const int* __restrict__ key_mask)
{
    const int q = blockIdx.x, h = blockIdx.y;
    float* row = g_score + (h * S + q) * S;
    const int tid = threadIdx.x;

    float v[4];
    float mx = -1e30f;
#pragma unroll
    for (int i = 0; i < 4; i++) {
        int k = tid + i * 128;
        float x = row[k];
        if (key_mask[k] == 0) x = -1e15f;
        v[i] = x;
        mx = fmaxf(mx, x);
    }
#pragma unroll
    for (int o = 16; o > 0; o >>= 1) mx = fmaxf(mx, __shfl_xor_sync(0xffffffffu, mx, o));
    __shared__ float redm[4];
    if ((tid & 31) == 0) redm[tid >> 5] = mx;
    __syncthreads();
    mx = fmaxf(fmaxf(redm[0], redm[1]), fmaxf(redm[2], redm[3]));

    float s = 0.f;
#pragma unroll
    for (int i = 0; i < 4; i++) { v[i] = __expf(v[i] - mx); s += v[i]; }
#pragma unroll
    for (int o = 16; o > 0; o >>= 1) s += __shfl_xor_sync(0xffffffffu, s, o);
    __shared__ float reds[4];
    if ((tid & 31) == 0) reds[tid >> 5] = s;
    __syncthreads();
    s = (reds[0] + reds[1]) + (reds[2] + reds[3]);
    float inv = 1.0f / s;
#pragma unroll
    for (int i = 0; i < 4; i++) row[tid + i * 128] = v[i] * inv;
}

// ---------------- 6) out[q][h*64+d] = sum_k attn[h][q][k] * vp[k][h*64+d] ----------------
__global__ void __launch_bounds__(128) out_kernel(float* __restrict__ out)
{
    const int q0 = blockIdx.x * 16;
    const int h  = blockIdx.y;
    const int tid = threadIdx.x;

    __shared__ float As[16][36];
    __shared__ float Vs[32][68];

    const int qg = tid >> 3;
    const int dg = tid & 7;

    unsigned long long acc[4] = {0ULL, 0ULL, 0ULL, 0ULL};

    for (int kc = 0; kc < 16; kc++) {
        {
            int f = tid;
            int qq = f >> 3;
            int k4 = (f & 7) * 4;
            float4 a = *reinterpret_cast<const float4*>(&g_score[(h * S + q0 + qq) * S + kc * 32 + k4]);
            *reinterpret_cast<float4*>(&As[qq][k4]) = a;
        }
#pragma unroll
        for (int t = 0; t < 4; t++) {
            int f = tid + t * 128;
            int k = f >> 4;
            int d4 = (f & 15) * 4;
            float4 a = *reinterpret_cast<const float4*>(&g_vp[(kc * 32 + k) * H + h * HD + d4]);
            *reinterpret_cast<float4*>(&Vs[k][d4]) = a;
        }
        __syncthreads();
#pragma unroll
        for (int kk = 0; kk < 32; kk++) {
            float a = As[qg][kk];
            unsigned long long aa = pack2(a, a);
            ulonglong2 w0 = *reinterpret_cast<const ulonglong2*>(&Vs[kk][dg * 8]);
            ulonglong2 w1 = *reinterpret_cast<const ulonglong2*>(&Vs[kk][dg * 8 + 4]);
            acc[0] = ffma2(aa, w0.x, acc[0]);
            acc[1] = ffma2(aa, w0.y, acc[1]);
            acc[2] = ffma2(aa, w1.x, acc[2]);
            acc[3] = ffma2(aa, w1.y, acc[3]);
        }
        __syncthreads();
    }
    float r[8];
#pragma unroll
    for (int j = 0; j < 4; j++) unpack2(acc[j], r[2 * j], r[2 * j + 1]);
    float* dst = &out[(q0 + qg) * H + h * HD + dg * 8];
    *reinterpret_cast<float4*>(&dst[0]) = make_float4(r[0], r[1], r[2], r[3]);
    *reinterpret_cast<float4*>(&dst[4]) = make_float4(r[4], r[5], r[6], r[7]);
}

// ---------------- launch ----------------
extern "C" void kernel_launch(void* const* d_in, const int* in_sizes, int n_in,
                              void* d_out, int out_size)
{
    (void)in_sizes; (void)n_in; (void)out_size;
    const float* key      = (const float*)d_in[0];
    const float* query    = (const float*)d_in[1];
    const float* value    = (const float*)d_in[2];
    const float* pos      = (const float*)d_in[3];
    const int*   key_mask = (const int*)d_in[4];
    const float* Wk = (const float*)d_in[5];
    const float* bk = (const float*)d_in[6];
    const float* Wq = (const float*)d_in[7];
    const float* bq = (const float*)d_in[8];
    const float* Wv = (const float*)d_in[9];
    const float* bv = (const float*)d_in[10];
    const float* Wr = (const float*)d_in[11];
    const float* br = (const float*)d_in[12];
    const float* u_bias = (const float*)d_in[13];
    const float* v_bias = (const float*)d_in[14];
    float* out = (float*)d_out;

    proj_kernel<<<dim3(8, 12, 3), 128>>>(query, key, value, Wq, bq, Wk, bk, Wv, bv);
    tt_kernel<<<dim3(12, 32), 128>>>(Wr, v_bias);
    cbias_kernel<<<48, 128>>>(br, v_bias);
    ac_kernel<<<dim3(8, 8, 12), 128>>>(u_bias);

    cudaFuncSetAttribute(bd_kernel, cudaFuncAttributeMaxDynamicSharedMemorySize, BD_SMEM_BYTES);
    bd_kernel<<<dim3(2, S), 128, BD_SMEM_BYTES>>>(pos);

    softmax_kernel<<<dim3(S, NH), 128>>>(key_mask);
    out_kernel<<<dim3(32, NH), 128>>>(out);
}

// round 3
// speedup vs baseline: 1.3600x; 1.0408x over previous
#include <cuda_runtime.h>

#define S 512
#define H 768
#define NH 12
#define HD 64

// ---------------- scratch (static device memory; no allocation) ----------------
__device__ float g_qp[S * H];            // query proj [s][c]
__device__ float g_kp[S * H];            // key proj
__device__ float g_vp[S * H];            // value proj
__device__ float g_tt[NH * S * H];       // t[h][q][e]
__device__ float g_cb[NH * S];           // cb[h][q]
__device__ float g_score[NH * S * S];    // score/attn [h][q][k]

// ---------------- f32x2 helpers ----------------
__device__ __forceinline__ unsigned long long pack2(float a, float b) {
    unsigned long long r;
    asm("mov.b64 %0, {%1, %2};" : "=l"(r) : "r"(__float_as_uint(a)), "r"(__float_as_uint(b)));
    return r;
}
__device__ __forceinline__ void unpack2(unsigned long long v, float& a, float& b) {
    unsigned int x, y;
    asm("mov.b64 {%0, %1}, %2;" : "=r"(x), "=r"(y) : "l"(v));
    a = __uint_as_float(x); b = __uint_as_float(y);
}
__device__ __forceinline__ unsigned long long ffma2(unsigned long long a, unsigned long long b,
                                                    unsigned long long c) {
    unsigned long long d;
    asm("fma.rn.f32x2 %0, %1, %2, %3;" : "=l"(d) : "l"(a), "l"(b), "l"(c));
    return d;
}
__device__ __forceinline__ void cp_async16(unsigned int smem_addr, const void* gptr) {
    asm volatile("cp.async.cg.shared.global [%0], [%1], 16;" :: "r"(smem_addr), "l"(gptr));
}
__device__ __forceinline__ void cp_commit() {
    asm volatile("cp.async.commit_group;" ::: "memory");
}
template <int N>
__device__ __forceinline__ void cp_wait() {
    asm volatile("cp.async.wait_group %0;" :: "n"(N) : "memory");
}

// ---------------- 1) proj: C = A @ W^T + b ; tiles 64s x 32c, K-tile 64 ----------------
__global__ void __launch_bounds__(128) proj_kernel(
    const float* __restrict__ q_in, const float* __restrict__ k_in, const float* __restrict__ v_in,
    const float* __restrict__ Wq, const float* __restrict__ bq,
    const float* __restrict__ Wk, const float* __restrict__ bk,
    const float* __restrict__ Wv, const float* __restrict__ bv)
{
    const float* A; const float* W; const float* bias; float* C;
    if (blockIdx.z == 0)      { A = q_in; W = Wq; bias = bq; C = g_qp; }
    else if (blockIdx.z == 1) { A = k_in; W = Wk; bias = bk; C = g_kp; }
    else                      { A = v_in; W = Wv; bias = bv; C = g_vp; }

    const int s0 = blockIdx.x * 64;
    const int c0 = blockIdx.y * 32;
    const int tid = threadIdx.x;

    __shared__ float Ast[64][68];   // [k][s]
    __shared__ float Ws2[64][36];   // [k][c]

    const int sg = tid >> 3;        // 0..15 -> s rows sg*4..+3
    const int cg = tid & 7;         // 0..7  -> c cols cg*4..+3

    unsigned long long acc[4][2];
#pragma unroll
    for (int i = 0; i < 4; i++) { acc[i][0] = 0ULL; acc[i][1] = 0ULL; }

    for (int kt = 0; kt < 12; kt++) {
        const int kb = kt * 64;
        // stage Ast transposed: 64s x 64k
#pragma unroll
        for (int t = 0; t < 8; t++) {
            int f = tid + t * 128;
            int s = f >> 4;
            int k4 = (f & 15) * 4;
            float4 a = *reinterpret_cast<const float4*>(&A[(s0 + s) * H + kb + k4]);
            Ast[k4 + 0][s] = a.x; Ast[k4 + 1][s] = a.y;
            Ast[k4 + 2][s] = a.z; Ast[k4 + 3][s] = a.w;
        }
        // stage Ws2 transposed: 32c x 64k
#pragma unroll
        for (int t = 0; t < 4; t++) {
            int f = tid + t * 128;
            int c = f >> 4;
            int k4 = (f & 15) * 4;
            float4 a = *reinterpret_cast<const float4*>(&W[(c0 + c) * H + kb + k4]);
            Ws2[k4 + 0][c] = a.x; Ws2[k4 + 1][c] = a.y;
            Ws2[k4 + 2][c] = a.z; Ws2[k4 + 3][c] = a.w;
        }
        __syncthreads();
#pragma unroll
        for (int kk = 0; kk < 64; kk++) {
            float4 a4 = *reinterpret_cast<const float4*>(&Ast[kk][sg * 4]);
            ulonglong2 b = *reinterpret_cast<const ulonglong2*>(&Ws2[kk][cg * 4]);
#pragma unroll
            for (int i = 0; i < 4; i++) {
                float av = (&a4.x)[i];
                unsigned long long pp = pack2(av, av);
                acc[i][0] = ffma2(pp, b.x, acc[i][0]);
                acc[i][1] = ffma2(pp, b.y, acc[i][1]);
            }
        }
        __syncthreads();
    }
#pragma unroll
    for (int i = 0; i < 4; i++) {
        int s = s0 + sg * 4 + i;
#pragma unroll
        for (int j = 0; j < 2; j++) {
            float lo, hi; unpack2(acc[i][j], lo, hi);
            int c = c0 + cg * 4 + 2 * j;
            float2 r2; r2.x = lo + bias[c]; r2.y = hi + bias[c + 1];
            *reinterpret_cast<float2*>(&C[s * H + c]) = r2;
        }
    }
}

// ---------------- 2) t[h][q][e] = sum_d (qp + vb) * Wr[h*64+d][e]; 32q x 64e ----------------
__global__ void __launch_bounds__(128) tt_kernel(const float* __restrict__ Wr,
                                                 const float* __restrict__ v_bias)
{
    const int e0 = blockIdx.x * 64;
    const int q0 = blockIdx.y * 32;
    const int tid = threadIdx.x;

    __shared__ float Qst[64][36];   // [d][q]
    __shared__ float Ws[64][68];    // [d][e]

    const int qg = tid >> 4;        // 0..7  -> q rows qg*4..+3
    const int eg = tid & 15;        // 0..15 -> e cols eg*4..+3

    for (int h = 0; h < NH; h++) {
        // stage Qst transposed (+v_bias): 32q x 64d
#pragma unroll
        for (int t = 0; t < 4; t++) {
            int f = tid + t * 128;
            int q = f >> 4;
            int d4 = (f & 15) * 4;
            float4 a = *reinterpret_cast<const float4*>(&g_qp[(q0 + q) * H + h * HD + d4]);
            float4 b = *reinterpret_cast<const float4*>(&v_bias[h * HD + d4]);
            Qst[d4 + 0][q] = a.x + b.x; Qst[d4 + 1][q] = a.y + b.y;
            Qst[d4 + 2][q] = a.z + b.z; Qst[d4 + 3][q] = a.w + b.w;
        }
        // stage Ws natural: 64d x 64e
#pragma unroll
        for (int t = 0; t < 8; t++) {
            int f = tid + t * 128;
            int d = f >> 4;
            int e4 = (f & 15) * 4;
            float4 a = *reinterpret_cast<const float4*>(&Wr[(h * HD + d) * H + e0 + e4]);
            *reinterpret_cast<float4*>(&Ws[d][e4]) = a;
        }
        __syncthreads();

        unsigned long long acc[4][2];
#pragma unroll
        for (int i = 0; i < 4; i++) { acc[i][0] = 0ULL; acc[i][1] = 0ULL; }

#pragma unroll
        for (int d = 0; d < HD; d++) {
            float4 a4 = *reinterpret_cast<const float4*>(&Qst[d][qg * 4]);
            ulonglong2 b = *reinterpret_cast<const ulonglong2*>(&Ws[d][eg * 4]);
#pragma unroll
            for (int i = 0; i < 4; i++) {
                float av = (&a4.x)[i];
                unsigned long long pp = pack2(av, av);
                acc[i][0] = ffma2(pp, b.x, acc[i][0]);
                acc[i][1] = ffma2(pp, b.y, acc[i][1]);
            }
        }
#pragma unroll
        for (int i = 0; i < 4; i++) {
            int q = q0 + qg * 4 + i;
#pragma unroll
            for (int j = 0; j < 2; j++) {
                float lo, hi; unpack2(acc[i][j], lo, hi);
                float2 r2; r2.x = lo; r2.y = hi;
                *reinterpret_cast<float2*>(&g_tt[(h * S + q) * H + e0 + eg * 4 + 2 * j]) = r2;
            }
        }
        __syncthreads();
    }
}

// ---------------- 2b) cb[h][q] = sum_d (qp + vb) * br ----------------
__global__ void __launch_bounds__(128) cbias_kernel(const float* __restrict__ br,
                                                    const float* __restrict__ v_bias)
{
    int idx = blockIdx.x * blockDim.x + threadIdx.x;
    if (idx >= NH * S) return;
    int h = idx / S, q = idx % S;
    float s = 0.f;
#pragma unroll 8
    for (int d = 0; d < HD; d++)
        s += (g_qp[q * H + h * HD + d] + v_bias[h * HD + d]) * br[h * HD + d];
    g_cb[idx] = s;
}

// ---------------- 3) AC[h][q][k] = sum_d (qp + u) * kp  (into g_score); 64q x 64k ----------------
__global__ void __launch_bounds__(128) ac_kernel(const float* __restrict__ u_bias)
{
    const int k0 = blockIdx.x * 64;
    const int q0 = blockIdx.y * 64;
    const int h  = blockIdx.z;
    const int tid = threadIdx.x;

    __shared__ float Qst[64][68];   // [d][q]
    __shared__ float Ks[64][68];    // [d][k]

    const int sg = tid >> 3;        // 0..15 -> q rows sg*4..+3
    const int kg = tid & 7;         // 0..7  -> k cols kg*8..+7

    // stage Qst transposed (+u): 64q x 64d
#pragma unroll
    for (int t = 0; t < 8; t++) {
        int f = tid + t * 128;
        int q = f >> 4;
        int d4 = (f & 15) * 4;
        float4 a = *reinterpret_cast<const float4*>(&g_qp[(q0 + q) * H + h * HD + d4]);
        float4 u = *reinterpret_cast<const float4*>(&u_bias[h * HD + d4]);
        Qst[d4 + 0][q] = a.x + u.x; Qst[d4 + 1][q] = a.y + u.y;
        Qst[d4 + 2][q] = a.z + u.z; Qst[d4 + 3][q] = a.w + u.w;
    }
    // stage Ks transposed: 64k x 64d
#pragma unroll
    for (int t = 0; t < 8; t++) {
        int f = tid + t * 128;
        int k = f >> 4;
        int d4 = (f & 15) * 4;
        float4 a = *reinterpret_cast<const float4*>(&g_kp[(k0 + k) * H + h * HD + d4]);
        Ks[d4 + 0][k] = a.x; Ks[d4 + 1][k] = a.y; Ks[d4 + 2][k] = a.z; Ks[d4 + 3][k] = a.w;
    }
    __syncthreads();

    unsigned long long acc[4][4];
#pragma unroll
    for (int i = 0; i < 4; i++)
#pragma unroll
        for (int j = 0; j < 4; j++) acc[i][j] = 0ULL;

#pragma unroll
    for (int d = 0; d < HD; d++) {
        float4 a4 = *reinterpret_cast<const float4*>(&Qst[d][sg * 4]);
        ulonglong2 b0 = *reinterpret_cast<const ulonglong2*>(&Ks[d][kg * 8]);
        ulonglong2 b1 = *reinterpret_cast<const ulonglong2*>(&Ks[d][kg * 8 + 4]);
#pragma unroll
        for (int i = 0; i < 4; i++) {
            float av = (&a4.x)[i];
            unsigned long long pp = pack2(av, av);
            acc[i][0] = ffma2(pp, b0.x, acc[i][0]);
            acc[i][1] = ffma2(pp, b0.y, acc[i][1]);
            acc[i][2] = ffma2(pp, b1.x, acc[i][2]);
            acc[i][3] = ffma2(pp, b1.y, acc[i][3]);
        }
    }
#pragma unroll
    for (int i = 0; i < 4; i++) {
        int q = q0 + sg * 4 + i;
#pragma unroll
        for (int j = 0; j < 4; j++) {
            int k = k0 + kg * 8 + 2 * j;
            *reinterpret_cast<unsigned long long*>(&g_score[(h * S + q) * S + k]) = acc[i][j];
        }
    }
}

// ---------------- 4) BD + fuse: score = (AC + cb + sum_e pos*t) / 8 ----------------
// grid (4, 512): one q per block-row, 128 keys per block; 128 threads, 1 key each.
// 4-deep cp.async ring buffer, prefetch distance 2, single barrier per chunk.
#define BD_E 32                   // e-chunk width
#define BD_PAD 36                 // padded row (floats)
#define BD_NCH (H / BD_E)         // 24 chunks
#define BD_TS (H * NH)            // t2s floats: [e][h]
#define BD_BUF (128 * BD_PAD)     // one pos buffer (4608 floats)
#define BD_SMEM_BYTES ((BD_TS + 4 * BD_BUF) * 4)

__device__ __forceinline__ void bd_issue(const float* prow, int ch, float* buf, int tid)
{
    unsigned int dbase = (unsigned int)__cvta_generic_to_shared(buf);
    const float* src = prow + ch * BD_E;
#pragma unroll
    for (int t = 0; t < 8; t++) {
        int seg = tid + t * 128;          // 1024 segs: 128 rows x 8 float4
        int row = seg >> 3;
        int c4  = (seg & 7) * 4;
        cp_async16(dbase + (unsigned)(row * BD_PAD + c4) * 4, src + (long)row * H + c4);
    }
}

__global__ void __launch_bounds__(128) bd_kernel(const float* __restrict__ pos)
{
    extern __shared__ float sm[];
    float* t2s = sm;                        // [e*12 + h]
    float* bufs[4];
    bufs[0] = sm + BD_TS;
    bufs[1] = sm + BD_TS + BD_BUF;
    bufs[2] = sm + BD_TS + 2 * BD_BUF;
    bufs[3] = sm + BD_TS + 3 * BD_BUF;

    const int q   = blockIdx.y;
    const int k0  = blockIdx.x * 128;
    const int tid = threadIdx.x;

    const float* prow = pos + ((long)q * S + k0) * H;

    // prologue: prefetch chunks 0 and 1
    bd_issue(prow, 0, bufs[0], tid); cp_commit();
    bd_issue(prow, 1, bufs[1], tid); cp_commit();

    // stage t2s: transpose g_tt[h][q][e] -> t2s[e][h]; 2304 float4 / 128 = 18
#pragma unroll
    for (int t = 0; t < 18; t++) {
        int f = tid + t * 128;
        int h = f / 192;
        int r = f - h * 192;
        int e = r * 4;
        float4 v4 = *reinterpret_cast<const float4*>(&g_tt[(h * S + q) * H + e]);
        t2s[(e + 0) * 12 + h] = v4.x;
        t2s[(e + 1) * 12 + h] = v4.y;
        t2s[(e + 2) * 12 + h] = v4.z;
        t2s[(e + 3) * 12 + h] = v4.w;
    }

    unsigned long long acc[6];
#pragma unroll
    for (int j = 0; j < 6; j++) acc[j] = 0ULL;

    const int base36 = tid * BD_PAD;

    for (int ch = 0; ch < BD_NCH; ch++) {
        if (ch + 2 < BD_NCH) {
            bd_issue(prow, ch + 2, bufs[(ch + 2) & 3], tid);
            cp_commit();
            cp_wait<2>();          // chunk ch complete; ch+1, ch+2 in flight
        } else if (ch + 1 < BD_NCH) {
            cp_wait<1>();
        } else {
            cp_wait<0>();
        }
        __syncthreads();           // single barrier: chunk ch visible to all;
                                   // also guarantees buf[(ch+2)&3] fully consumed
                                   // (its last reader was compute(ch-2))

        const float* bp = bufs[ch & 3];
        const int e0 = ch * BD_E;
#pragma unroll
        for (int j = 0; j < 8; j++) {
            float4 pa = *reinterpret_cast<const float4*>(&bp[base36 + 4 * j]);
            const float* tw = &t2s[(e0 + 4 * j) * 12];
#pragma unroll
            for (int i = 0; i < 4; i++) {
                float p0 = (&pa.x)[i];
                unsigned long long pp = pack2(p0, p0);
                const ulonglong2 w0 = *reinterpret_cast<const ulonglong2*>(&tw[i * 12 + 0]);
                const ulonglong2 w1 = *reinterpret_cast<const ulonglong2*>(&tw[i * 12 + 4]);
                const ulonglong2 w2 = *reinterpret_cast<const ulonglong2*>(&tw[i * 12 + 8]);
                acc[0] = ffma2(pp, w0.x, acc[0]);
                acc[1] = ffma2(pp, w0.y, acc[1]);
                acc[2] = ffma2(pp, w1.x, acc[2]);
                acc[3] = ffma2(pp, w1.y, acc[3]);
                acc[4] = ffma2(pp, w2.x, acc[4]);
                acc[5] = ffma2(pp, w2.y, acc[5]);
            }
        }
    }

    const int k = k0 + tid;
#pragma unroll
    for (int j = 0; j < 6; j++) {
        float a0, a1;
        unpack2(acc[j], a0, a1);   // heads 2j, 2j+1
        int h0 = 2 * j, h1 = 2 * j + 1;
        float c0 = g_cb[h0 * S + q];
        float c1 = g_cb[h1 * S + q];
        int i0 = (h0 * S + q) * S + k;
        int i1 = (h1 * S + q) * S + k;
        g_score[i0] = (g_score[i0] + c0 + a0) * 0.125f;
        g_score[i1] = (g_score[i1] + c1 + a1) * 0.125f;
    }
}

// ---------------- 5) softmax over k with mask ----------------
__global__ void __launch_bounds__(128) softmax_kernel(const int* __restrict__ key_mask)
{
    const int q = blockIdx.x, h = blockIdx.y;
    float* row = g_score + (h * S + q) * S;
    const int tid = threadIdx.x;

    float v[4];
    float mx = -1e30f;
#pragma unroll
    for (int i = 0; i < 4; i++) {
        int k = tid + i * 128;
        float x = row[k];
        if (key_mask[k] == 0) x = -1e15f;
        v[i] = x;
        mx = fmaxf(mx, x);
    }
#pragma unroll
    for (int o = 16; o > 0; o >>= 1) mx = fmaxf(mx, __shfl_xor_sync(0xffffffffu, mx, o));
    __shared__ float redm[4];
    if ((tid & 31) == 0) redm[tid >> 5] = mx;
    __syncthreads();
    mx = fmaxf(fmaxf(redm[0], redm[1]), fmaxf(redm[2], redm[3]));

    float s = 0.f;
#pragma unroll
    for (int i = 0; i < 4; i++) { v[i] = __expf(v[i] - mx); s += v[i]; }
#pragma unroll
    for (int o = 16; o > 0; o >>= 1) s += __shfl_xor_sync(0xffffffffu, s, o);
    __shared__ float reds[4];
    if ((tid & 31) == 0) reds[tid >> 5] = s;
    __syncthreads();
    s = (reds[0] + reds[1]) + (reds[2] + reds[3]);
    float inv = 1.0f / s;
#pragma unroll
    for (int i = 0; i < 4; i++) row[tid + i * 128] = v[i] * inv;
}

// ---------------- 6) out[q][h*64+d] = sum_k attn[h][q][k] * vp[k][h*64+d]; 32q x 64d ----------------
__global__ void __launch_bounds__(128) out_kernel(float* __restrict__ out)
{
    const int q0 = blockIdx.x * 32;
    const int h  = blockIdx.y;
    const int tid = threadIdx.x;

    __shared__ float At[64][36];   // [k][q]
    __shared__ float Vs[64][68];   // [k][d]

    const int qg = tid >> 4;       // 0..7  -> q rows qg*4..+3
    const int dg = tid & 15;       // 0..15 -> d cols dg*4..+3

    unsigned long long acc[4][2];
#pragma unroll
    for (int i = 0; i < 4; i++) { acc[i][0] = 0ULL; acc[i][1] = 0ULL; }

    for (int kc = 0; kc < 8; kc++) {
        // stage At transposed: 32q x 64k
#pragma unroll
        for (int t = 0; t < 4; t++) {
            int f = tid + t * 128;
            int q = f >> 4;
            int k4 = (f & 15) * 4;
            float4 a = *reinterpret_cast<const float4*>(&g_score[(h * S + q0 + q) * S + kc * 64 + k4]);
            At[k4 + 0][q] = a.x; At[k4 + 1][q] = a.y;
            At[k4 + 2][q] = a.z; At[k4 + 3][q] = a.w;
        }
        // stage Vs natural: 64k x 64d
#pragma unroll
        for (int t = 0; t < 8; t++) {
            int f = tid + t * 128;
            int k = f >> 4;
            int d4 = (f & 15) * 4;
            float4 a = *reinterpret_cast<const float4*>(&g_vp[(kc * 64 + k) * H + h * HD + d4]);
            *reinterpret_cast<float4*>(&Vs[k][d4]) = a;
        }
        __syncthreads();
#pragma unroll
        for (int kk = 0; kk < 64; kk++) {
            float4 a4 = *reinterpret_cast<const float4*>(&At[kk][qg * 4]);
            ulonglong2 b = *reinterpret_cast<const ulonglong2*>(&Vs[kk][dg * 4]);
#pragma unroll
            for (int i = 0; i < 4; i++) {
                float av = (&a4.x)[i];
                unsigned long long pp = pack2(av, av);
                acc[i][0] = ffma2(pp, b.x, acc[i][0]);
                acc[i][1] = ffma2(pp, b.y, acc[i][1]);
            }
        }
        __syncthreads();
    }
#pragma unroll
    for (int i = 0; i < 4; i++) {
        int q = q0 + qg * 4 + i;
#pragma unroll
        for (int j = 0; j < 2; j++) {
            float lo, hi; unpack2(acc[i][j], lo, hi);
            float2 r2; r2.x = lo; r2.y = hi;
            *reinterpret_cast<float2*>(&out[q * H + h * HD + dg * 4 + 2 * j]) = r2;
        }
    }
}

// ---------------- launch ----------------
extern "C" void kernel_launch(void* const* d_in, const int* in_sizes, int n_in,
                              void* d_out, int out_size)
{
    (void)in_sizes; (void)n_in; (void)out_size;
    const float* key      = (const float*)d_in[0];
    const float* query    = (const float*)d_in[1];
    const float* value    = (const float*)d_in[2];
    const float* pos      = (const float*)d_in[3];
    const int*   key_mask = (const int*)d_in[4];
    const float* Wk = (const float*)d_in[5];
    const float* bk = (const float*)d_in[6];
    const float* Wq = (const float*)d_in[7];
    const float* bq = (const float*)d_in[8];
    const float* Wv = (const float*)d_in[9];
    const float* bv = (const float*)d_in[10];
    const float* Wr = (const float*)d_in[11];
    const float* br = (const float*)d_in[12];
    const float* u_bias = (const float*)d_in[13];
    const float* v_bias = (const float*)d_in[14];
    float* out = (float*)d_out;

    proj_kernel<<<dim3(8, 24, 3), 128>>>(query, key, value, Wq, bq, Wk, bk, Wv, bv);
    tt_kernel<<<dim3(12, 16), 128>>>(Wr, v_bias);
    cbias_kernel<<<48, 128>>>(br, v_bias);
    ac_kernel<<<dim3(8, 8, 12), 128>>>(u_bias);

    cudaFuncSetAttribute(bd_kernel, cudaFuncAttributeMaxDynamicSharedMemorySize, BD_SMEM_BYTES);
    bd_kernel<<<dim3(4, S), 128, BD_SMEM_BYTES>>>(pos);

    softmax_kernel<<<dim3(S, NH), 128>>>(key_mask);
    out_kernel<<<dim3(16, NH), 128>>>(out);
}

// round 4
// speedup vs baseline: 1.5763x; 1.1591x over previous
#include <cuda_runtime.h>

#define S 512
#define H 768
#define NH 12
#define HD 64

// ---------------- scratch (static device memory; no allocation) ----------------
__device__ float g_qp[S * H];            // query proj [s][c]
__device__ float g_kp[S * H];            // key proj
__device__ float g_vp[S * H];            // value proj
__device__ float g_tt[NH * S * H];       // t[h][q][e]
__device__ float g_cb[NH * S];           // cb[h][q]
__device__ float g_score[NH * S * S];    // score/attn [h][q][k]

// ---------------- f32x2 helpers ----------------
__device__ __forceinline__ unsigned long long pack2(float a, float b) {
    unsigned long long r;
    asm("mov.b64 %0, {%1, %2};" : "=l"(r) : "r"(__float_as_uint(a)), "r"(__float_as_uint(b)));
    return r;
}
__device__ __forceinline__ void unpack2(unsigned long long v, float& a, float& b) {
    unsigned int x, y;
    asm("mov.b64 {%0, %1}, %2;" : "=r"(x), "=r"(y) : "l"(v));
    a = __uint_as_float(x); b = __uint_as_float(y);
}
__device__ __forceinline__ unsigned long long ffma2(unsigned long long a, unsigned long long b,
                                                    unsigned long long c) {
    unsigned long long d;
    asm("fma.rn.f32x2 %0, %1, %2, %3;" : "=l"(d) : "l"(a), "l"(b), "l"(c));
    return d;
}
__device__ __forceinline__ void cp_async16(unsigned int smem_addr, const void* gptr) {
    asm volatile("cp.async.cg.shared.global [%0], [%1], 16;" :: "r"(smem_addr), "l"(gptr));
}
__device__ __forceinline__ void cp_commit() {
    asm volatile("cp.async.commit_group;" ::: "memory");
}
template <int N>
__device__ __forceinline__ void cp_wait() {
    asm volatile("cp.async.wait_group %0;" :: "n"(N) : "memory");
}

// ---------------- 1) proj: C = A @ W^T + b ; 64s x 32c tile, K-tile 64, reg double-buffer ----------------
__global__ void __launch_bounds__(128) proj_kernel(
    const float* __restrict__ q_in, const float* __restrict__ k_in, const float* __restrict__ v_in,
    const float* __restrict__ Wq, const float* __restrict__ bq,
    const float* __restrict__ Wk, const float* __restrict__ bk,
    const float* __restrict__ Wv, const float* __restrict__ bv)
{
    const float* A; const float* W; const float* bias; float* C;
    if (blockIdx.z == 0)      { A = q_in; W = Wq; bias = bq; C = g_qp; }
    else if (blockIdx.z == 1) { A = k_in; W = Wk; bias = bk; C = g_kp; }
    else                      { A = v_in; W = Wv; bias = bv; C = g_vp; }

    const int s0 = blockIdx.x * 64;
    const int c0 = blockIdx.y * 32;
    const int tid = threadIdx.x;

    __shared__ float Ast[64][68];   // [k][s]
    __shared__ float Ws2[64][36];   // [k][c]

    const int sg = tid >> 3;        // 0..15 -> s rows sg*4..+3
    const int cg = tid & 7;         // 0..7  -> c cols cg*4..+3

    unsigned long long acc[4][2];
#pragma unroll
    for (int i = 0; i < 4; i++) { acc[i][0] = 0ULL; acc[i][1] = 0ULL; }

    float4 ra[8], rw[4];
    // prologue loads for kt = 0
#pragma unroll
    for (int t = 0; t < 8; t++) {
        int f = tid + t * 128;
        ra[t] = *reinterpret_cast<const float4*>(&A[(s0 + (f >> 4)) * H + (f & 15) * 4]);
    }
#pragma unroll
    for (int t = 0; t < 4; t++) {
        int f = tid + t * 128;
        rw[t] = *reinterpret_cast<const float4*>(&W[(c0 + (f >> 4)) * H + (f & 15) * 4]);
    }

    for (int kt = 0; kt < 12; kt++) {
        __syncthreads();   // previous compute done (no-op first iter)
#pragma unroll
        for (int t = 0; t < 8; t++) {
            int f = tid + t * 128;
            int s = f >> 4;
            int k4 = (f & 15) * 4;
            Ast[k4 + 0][s] = ra[t].x; Ast[k4 + 1][s] = ra[t].y;
            Ast[k4 + 2][s] = ra[t].z; Ast[k4 + 3][s] = ra[t].w;
        }
#pragma unroll
        for (int t = 0; t < 4; t++) {
            int f = tid + t * 128;
            int c = f >> 4;
            int k4 = (f & 15) * 4;
            Ws2[k4 + 0][c] = rw[t].x; Ws2[k4 + 1][c] = rw[t].y;
            Ws2[k4 + 2][c] = rw[t].z; Ws2[k4 + 3][c] = rw[t].w;
        }
        __syncthreads();

        if (kt + 1 < 12) {
            const int kb = (kt + 1) * 64;
#pragma unroll
            for (int t = 0; t < 8; t++) {
                int f = tid + t * 128;
                ra[t] = *reinterpret_cast<const float4*>(&A[(s0 + (f >> 4)) * H + kb + (f & 15) * 4]);
            }
#pragma unroll
            for (int t = 0; t < 4; t++) {
                int f = tid + t * 128;
                rw[t] = *reinterpret_cast<const float4*>(&W[(c0 + (f >> 4)) * H + kb + (f & 15) * 4]);
            }
        }

#pragma unroll
        for (int kk = 0; kk < 64; kk++) {
            float4 a4 = *reinterpret_cast<const float4*>(&Ast[kk][sg * 4]);
            ulonglong2 b = *reinterpret_cast<const ulonglong2*>(&Ws2[kk][cg * 4]);
#pragma unroll
            for (int i = 0; i < 4; i++) {
                float av = (&a4.x)[i];
                unsigned long long pp = pack2(av, av);
                acc[i][0] = ffma2(pp, b.x, acc[i][0]);
                acc[i][1] = ffma2(pp, b.y, acc[i][1]);
            }
        }
    }
#pragma unroll
    for (int i = 0; i < 4; i++) {
        int s = s0 + sg * 4 + i;
#pragma unroll
        for (int j = 0; j < 2; j++) {
            float lo, hi; unpack2(acc[i][j], lo, hi);
            int c = c0 + cg * 4 + 2 * j;
            float2 r2; r2.x = lo + bias[c]; r2.y = hi + bias[c + 1];
            *reinterpret_cast<float2*>(&C[s * H + c]) = r2;
        }
    }
}

// ---------------- 2) t[h][q][e] = sum_d (qp + vb) * Wr[h*64+d][e]; 32q x 64e ----------------
__global__ void __launch_bounds__(128) tt_kernel(const float* __restrict__ Wr,
                                                 const float* __restrict__ v_bias)
{
    const int e0 = blockIdx.x * 64;
    const int q0 = blockIdx.y * 32;
    const int tid = threadIdx.x;

    __shared__ float Qst[64][36];   // [d][q]
    __shared__ float Ws[64][68];    // [d][e]

    const int qg = tid >> 4;        // 0..7  -> q rows qg*4..+3
    const int eg = tid & 15;        // 0..15 -> e cols eg*4..+3

    for (int h = 0; h < NH; h++) {
#pragma unroll
        for (int t = 0; t < 4; t++) {
            int f = tid + t * 128;
            int q = f >> 4;
            int d4 = (f & 15) * 4;
            float4 a = *reinterpret_cast<const float4*>(&g_qp[(q0 + q) * H + h * HD + d4]);
            float4 b = *reinterpret_cast<const float4*>(&v_bias[h * HD + d4]);
            Qst[d4 + 0][q] = a.x + b.x; Qst[d4 + 1][q] = a.y + b.y;
            Qst[d4 + 2][q] = a.z + b.z; Qst[d4 + 3][q] = a.w + b.w;
        }
#pragma unroll
        for (int t = 0; t < 8; t++) {
            int f = tid + t * 128;
            int d = f >> 4;
            int e4 = (f & 15) * 4;
            float4 a = *reinterpret_cast<const float4*>(&Wr[(h * HD + d) * H + e0 + e4]);
            *reinterpret_cast<float4*>(&Ws[d][e4]) = a;
        }
        __syncthreads();

        unsigned long long acc[4][2];
#pragma unroll
        for (int i = 0; i < 4; i++) { acc[i][0] = 0ULL; acc[i][1] = 0ULL; }

#pragma unroll
        for (int d = 0; d < HD; d++) {
            float4 a4 = *reinterpret_cast<const float4*>(&Qst[d][qg * 4]);
            ulonglong2 b = *reinterpret_cast<const ulonglong2*>(&Ws[d][eg * 4]);
#pragma unroll
            for (int i = 0; i < 4; i++) {
                float av = (&a4.x)[i];
                unsigned long long pp = pack2(av, av);
                acc[i][0] = ffma2(pp, b.x, acc[i][0]);
                acc[i][1] = ffma2(pp, b.y, acc[i][1]);
            }
        }
#pragma unroll
        for (int i = 0; i < 4; i++) {
            int q = q0 + qg * 4 + i;
#pragma unroll
            for (int j = 0; j < 2; j++) {
                float lo, hi; unpack2(acc[i][j], lo, hi);
                float2 r2; r2.x = lo; r2.y = hi;
                *reinterpret_cast<float2*>(&g_tt[(h * S + q) * H + e0 + eg * 4 + 2 * j]) = r2;
            }
        }
        __syncthreads();
    }
}

// ---------------- 2b) cb[h][q] = sum_d (qp + vb) * br ----------------
__global__ void __launch_bounds__(128) cbias_kernel(const float* __restrict__ br,
                                                    const float* __restrict__ v_bias)
{
    int idx = blockIdx.x * blockDim.x + threadIdx.x;
    if (idx >= NH * S) return;
    int h = idx / S, q = idx % S;
    float s = 0.f;
#pragma unroll 8
    for (int d = 0; d < HD; d++)
        s += (g_qp[q * H + h * HD + d] + v_bias[h * HD + d]) * br[h * HD + d];
    g_cb[idx] = s;
}

// ---------------- 3) AC[h][q][k] = sum_d (qp + u) * kp  (into g_score); 64q x 64k ----------------
__global__ void __launch_bounds__(128) ac_kernel(const float* __restrict__ u_bias)
{
    const int k0 = blockIdx.x * 64;
    const int q0 = blockIdx.y * 64;
    const int h  = blockIdx.z;
    const int tid = threadIdx.x;

    __shared__ float Qst[64][68];   // [d][q]
    __shared__ float Ks[64][68];    // [d][k]

    const int sg = tid >> 3;        // 0..15 -> q rows sg*4..+3
    const int kg = tid & 7;         // 0..7  -> k cols kg*8..+7

#pragma unroll
    for (int t = 0; t < 8; t++) {
        int f = tid + t * 128;
        int q = f >> 4;
        int d4 = (f & 15) * 4;
        float4 a = *reinterpret_cast<const float4*>(&g_qp[(q0 + q) * H + h * HD + d4]);
        float4 u = *reinterpret_cast<const float4*>(&u_bias[h * HD + d4]);
        Qst[d4 + 0][q] = a.x + u.x; Qst[d4 + 1][q] = a.y + u.y;
        Qst[d4 + 2][q] = a.z + u.z; Qst[d4 + 3][q] = a.w + u.w;
    }
#pragma unroll
    for (int t = 0; t < 8; t++) {
        int f = tid + t * 128;
        int k = f >> 4;
        int d4 = (f & 15) * 4;
        float4 a = *reinterpret_cast<const float4*>(&g_kp[(k0 + k) * H + h * HD + d4]);
        Ks[d4 + 0][k] = a.x; Ks[d4 + 1][k] = a.y; Ks[d4 + 2][k] = a.z; Ks[d4 + 3][k] = a.w;
    }
    __syncthreads();

    unsigned long long acc[4][4];
#pragma unroll
    for (int i = 0; i < 4; i++)
#pragma unroll
        for (int j = 0; j < 4; j++) acc[i][j] = 0ULL;

#pragma unroll
    for (int d = 0; d < HD; d++) {
        float4 a4 = *reinterpret_cast<const float4*>(&Qst[d][sg * 4]);
        ulonglong2 b0 = *reinterpret_cast<const ulonglong2*>(&Ks[d][kg * 8]);
        ulonglong2 b1 = *reinterpret_cast<const ulonglong2*>(&Ks[d][kg * 8 + 4]);
#pragma unroll
        for (int i = 0; i < 4; i++) {
            float av = (&a4.x)[i];
            unsigned long long pp = pack2(av, av);
            acc[i][0] = ffma2(pp, b0.x, acc[i][0]);
            acc[i][1] = ffma2(pp, b0.y, acc[i][1]);
            acc[i][2] = ffma2(pp, b1.x, acc[i][2]);
            acc[i][3] = ffma2(pp, b1.y, acc[i][3]);
        }
    }
#pragma unroll
    for (int i = 0; i < 4; i++) {
        int q = q0 + sg * 4 + i;
#pragma unroll
        for (int j = 0; j < 4; j++) {
            int k = k0 + kg * 8 + 2 * j;
            *reinterpret_cast<unsigned long long*>(&g_score[(h * S + q) * S + k]) = acc[i][j];
        }
    }
}

// ---------------- 4) BD + fuse: score = (AC + cb + sum_e pos*t) / 8 ----------------
// grid (2, 512): one q per block-row, 256 keys per block, 128 threads (4 warps).
// Each warp owns 64 keys (2/thread) with its OWN double-buffered cp.async pipeline.
// NO block barriers in the main loop -> no convoy; warps self-pace against DRAM.
#define BD_E 32                   // e-chunk width
#define BD_PAD 36                 // padded row (floats)
#define BD_NCH (H / BD_E)         // 24 chunks
#define BD_TS (H * NH)            // t2s floats: [e][h]
#define BDW_BUF (64 * BD_PAD)     // one per-warp pos buffer (2304 floats = 9216 B)
#define BD_SMEM_BYTES ((BD_TS + 4 * 2 * BDW_BUF) * 4)   // 110592 B

__device__ __forceinline__ void bd_issue_warp(const float* src_base, int ch, float* buf, int lane)
{
    unsigned int dbase = (unsigned int)__cvta_generic_to_shared(buf);
    const float* src = src_base + ch * BD_E;
#pragma unroll
    for (int t = 0; t < 16; t++) {
        int seg = lane + t * 32;          // 512 segs: 64 rows x 8 float4
        int row = seg >> 3;
        int c4  = (seg & 7) * 4;
        cp_async16(dbase + (unsigned)(row * BD_PAD + c4) * 4, src + (long)row * H + c4);
    }
}

__global__ void __launch_bounds__(128) bd_kernel(const float* __restrict__ pos)
{
    extern __shared__ float sm[];
    float* t2s = sm;                        // [e*12 + h]
    const int tid  = threadIdx.x;
    const int wid  = tid >> 5;
    const int lane = tid & 31;
    float* wbuf0 = sm + BD_TS + wid * 2 * BDW_BUF;
    float* wbuf1 = wbuf0 + BDW_BUF;

    const int q  = blockIdx.y;
    const int k0 = blockIdx.x * 256;

    // this warp's 64 pos rows
    const float* psrc = pos + ((long)q * S + k0 + wid * 64) * H;

    // prologue: prefetch chunk 0 (warp-local)
    bd_issue_warp(psrc, 0, wbuf0, lane);
    cp_commit();

    // stage t2s: transpose g_tt[h][q][e] -> t2s[e][h]; 2304 float4 / 128 = 18
#pragma unroll
    for (int t = 0; t < 18; t++) {
        int f = tid + t * 128;
        int h = f / 192;
        int r = f - h * 192;
        int e = r * 4;
        float4 v4 = *reinterpret_cast<const float4*>(&g_tt[(h * S + q) * H + e]);
        t2s[(e + 0) * 12 + h] = v4.x;
        t2s[(e + 1) * 12 + h] = v4.y;
        t2s[(e + 2) * 12 + h] = v4.z;
        t2s[(e + 3) * 12 + h] = v4.w;
    }
    __syncthreads();    // t2s visible to all; only block-wide barrier

    unsigned long long acc0[6], acc1[6];
#pragma unroll
    for (int j = 0; j < 6; j++) { acc0[j] = 0ULL; acc1[j] = 0ULL; }

    const int ra36 = lane * BD_PAD;
    const int rb36 = (lane + 32) * BD_PAD;

    for (int ch = 0; ch < BD_NCH; ch++) {
        if (ch + 1 < BD_NCH) {
            bd_issue_warp(psrc, ch + 1, ((ch + 1) & 1) ? wbuf1 : wbuf0, lane);
            cp_commit();
            cp_wait<1>();          // chunk ch complete for THIS lane
        } else {
            cp_wait<0>();
        }
        __syncwarp();              // all lanes' chunk-ch groups complete + smem ordering

        const float* bp = (ch & 1) ? wbuf1 : wbuf0;
        const int e0 = ch * BD_E;
#pragma unroll
        for (int j = 0; j < 8; j++) {
            float4 pa = *reinterpret_cast<const float4*>(&bp[ra36 + 4 * j]);
            float4 pb = *reinterpret_cast<const float4*>(&bp[rb36 + 4 * j]);
            const float* tw = &t2s[(e0 + 4 * j) * 12];
#pragma unroll
            for (int i = 0; i < 4; i++) {
                float p0 = (&pa.x)[i];
                float p1 = (&pb.x)[i];
                unsigned long long pp0 = pack2(p0, p0);
                unsigned long long pp1 = pack2(p1, p1);
                const ulonglong2 w0 = *reinterpret_cast<const ulonglong2*>(&tw[i * 12 + 0]);
                const ulonglong2 w1 = *reinterpret_cast<const ulonglong2*>(&tw[i * 12 + 4]);
                const ulonglong2 w2 = *reinterpret_cast<const ulonglong2*>(&tw[i * 12 + 8]);
                acc0[0] = ffma2(pp0, w0.x, acc0[0]);
                acc0[1] = ffma2(pp0, w0.y, acc0[1]);
                acc0[2] = ffma2(pp0, w1.x, acc0[2]);
                acc0[3] = ffma2(pp0, w1.y, acc0[3]);
                acc0[4] = ffma2(pp0, w2.x, acc0[4]);
                acc0[5] = ffma2(pp0, w2.y, acc0[5]);
                acc1[0] = ffma2(pp1, w0.x, acc1[0]);
                acc1[1] = ffma2(pp1, w0.y, acc1[1]);
                acc1[2] = ffma2(pp1, w1.x, acc1[2]);
                acc1[3] = ffma2(pp1, w1.y, acc1[3]);
                acc1[4] = ffma2(pp1, w2.x, acc1[4]);
                acc1[5] = ffma2(pp1, w2.y, acc1[5]);
            }
        }
        __syncwarp();              // all lanes done reading buf before next overwrite
    }

    const int ka = k0 + wid * 64 + lane;
    const int kb = ka + 32;
#pragma unroll
    for (int j = 0; j < 6; j++) {
        float a0, a1, b0, b1;
        unpack2(acc0[j], a0, a1);   // key ka, heads 2j, 2j+1
        unpack2(acc1[j], b0, b1);   // key kb
        int h0 = 2 * j, h1 = 2 * j + 1;
        float c0 = g_cb[h0 * S + q];
        float c1 = g_cb[h1 * S + q];
        int i0 = (h0 * S + q) * S;
        int i1 = (h1 * S + q) * S;
        g_score[i0 + ka] = (g_score[i0 + ka] + c0 + a0) * 0.125f;
        g_score[i1 + ka] = (g_score[i1 + ka] + c1 + a1) * 0.125f;
        g_score[i0 + kb] = (g_score[i0 + kb] + c0 + b0) * 0.125f;
        g_score[i1 + kb] = (g_score[i1 + kb] + c1 + b1) * 0.125f;
    }
}

// ---------------- 5) softmax over k with mask ----------------
__global__ void __launch_bounds__(128) softmax_kernel(const int* __restrict__ key_mask)
{
    const int q = blockIdx.x, h = blockIdx.y;
    float* row = g_score + (h * S + q) * S;
    const int tid = threadIdx.x;

    float v[4];
    float mx = -1e30f;
#pragma unroll
    for (int i = 0; i < 4; i++) {
        int k = tid + i * 128;
        float x = row[k];
        if (key_mask[k] == 0) x = -1e15f;
        v[i] = x;
        mx = fmaxf(mx, x);
    }
#pragma unroll
    for (int o = 16; o > 0; o >>= 1) mx = fmaxf(mx, __shfl_xor_sync(0xffffffffu, mx, o));
    __shared__ float redm[4];
    if ((tid & 31) == 0) redm[tid >> 5] = mx;
    __syncthreads();
    mx = fmaxf(fmaxf(redm[0], redm[1]), fmaxf(redm[2], redm[3]));

    float s = 0.f;
#pragma unroll
    for (int i = 0; i < 4; i++) { v[i] = __expf(v[i] - mx); s += v[i]; }
#pragma unroll
    for (int o = 16; o > 0; o >>= 1) s += __shfl_xor_sync(0xffffffffu, s, o);
    __shared__ float reds[4];
    if ((tid & 31) == 0) reds[tid >> 5] = s;
    __syncthreads();
    s = (reds[0] + reds[1]) + (reds[2] + reds[3]);
    float inv = 1.0f / s;
#pragma unroll
    for (int i = 0; i < 4; i++) row[tid + i * 128] = v[i] * inv;
}

// ---------------- 6) out[q][h*64+d] = sum_k attn[h][q][k] * vp[k][h*64+d]; 32q x 64d ----------------
__global__ void __launch_bounds__(128) out_kernel(float* __restrict__ out)
{
    const int q0 = blockIdx.x * 32;
    const int h  = blockIdx.y;
    const int tid = threadIdx.x;

    __shared__ float At[64][36];   // [k][q]
    __shared__ float Vs[64][68];   // [k][d]

    const int qg = tid >> 4;       // 0..7  -> q rows qg*4..+3
    const int dg = tid & 15;       // 0..15 -> d cols dg*4..+3

    unsigned long long acc[4][2];
#pragma unroll
    for (int i = 0; i < 4; i++) { acc[i][0] = 0ULL; acc[i][1] = 0ULL; }

    for (int kc = 0; kc < 8; kc++) {
#pragma unroll
        for (int t = 0; t < 4; t++) {
            int f = tid + t * 128;
            int q = f >> 4;
            int k4 = (f & 15) * 4;
            float4 a = *reinterpret_cast<const float4*>(&g_score[(h * S + q0 + q) * S + kc * 64 + k4]);
            At[k4 + 0][q] = a.x; At[k4 + 1][q] = a.y;
            At[k4 + 2][q] = a.z; At[k4 + 3][q] = a.w;
        }
#pragma unroll
        for (int t = 0; t < 8; t++) {
            int f = tid + t * 128;
            int k = f >> 4;
            int d4 = (f & 15) * 4;
            float4 a = *reinterpret_cast<const float4*>(&g_vp[(kc * 64 + k) * H + h * HD + d4]);
            *reinterpret_cast<float4*>(&Vs[k][d4]) = a;
        }
        __syncthreads();
#pragma unroll
        for (int kk = 0; kk < 64; kk++) {
            float4 a4 = *reinterpret_cast<const float4*>(&At[kk][qg * 4]);
            ulonglong2 b = *reinterpret_cast<const ulonglong2*>(&Vs[kk][dg * 4]);
#pragma unroll
            for (int i = 0; i < 4; i++) {
                float av = (&a4.x)[i];
                unsigned long long pp = pack2(av, av);
                acc[i][0] = ffma2(pp, b.x, acc[i][0]);
                acc[i][1] = ffma2(pp, b.y, acc[i][1]);
            }
        }
        __syncthreads();
    }
#pragma unroll
    for (int i = 0; i < 4; i++) {
        int q = q0 + qg * 4 + i;
#pragma unroll
        for (int j = 0; j < 2; j++) {
            float lo, hi; unpack2(acc[i][j], lo, hi);
            float2 r2; r2.x = lo; r2.y = hi;
            *reinterpret_cast<float2*>(&out[q * H + h * HD + dg * 4 + 2 * j]) = r2;
        }
    }
}

// ---------------- launch ----------------
extern "C" void kernel_launch(void* const* d_in, const int* in_sizes, int n_in,
                              void* d_out, int out_size)
{
    (void)in_sizes; (void)n_in; (void)out_size;
    const float* key      = (const float*)d_in[0];
    const float* query    = (const float*)d_in[1];
    const float* value    = (const float*)d_in[2];
    const float* pos      = (const float*)d_in[3];
    const int*   key_mask = (const int*)d_in[4];
    const float* Wk = (const float*)d_in[5];
    const float* bk = (const float*)d_in[6];
    const float* Wq = (const float*)d_in[7];
    const float* bq = (const float*)d_in[8];
    const float* Wv = (const float*)d_in[9];
    const float* bv = (const float*)d_in[10];
    const float* Wr = (const float*)d_in[11];
    const float* br = (const float*)d_in[12];
    const float* u_bias = (const float*)d_in[13];
    const float* v_bias = (const float*)d_in[14];
    float* out = (float*)d_out;

    proj_kernel<<<dim3(8, 24, 3), 128>>>(query, key, value, Wq, bq, Wk, bk, Wv, bv);
    tt_kernel<<<dim3(12, 16), 128>>>(Wr, v_bias);
    cbias_kernel<<<48, 128>>>(br, v_bias);
    ac_kernel<<<dim3(8, 8, 12), 128>>>(u_bias);

    cudaFuncSetAttribute(bd_kernel, cudaFuncAttributeMaxDynamicSharedMemorySize, BD_SMEM_BYTES);
    bd_kernel<<<dim3(2, S), 128, BD_SMEM_BYTES>>>(pos);

    softmax_kernel<<<dim3(S, NH), 128>>>(key_mask);
    out_kernel<<<dim3(16, NH), 128>>>(out);
}